// round 11
// baseline (speedup 1.0000x reference)
#include <cuda_runtime.h>
#include <math.h>
#include <stdint.h>

#define BB 8
#define NN 1024
#define DD 512
#define HH 8
#define HD 64

__device__ float g_qT[BB*HH*HD*NN];    // [B,H,d,n]   16MB (tf32-rounded)
__device__ float g_kT[BB*HH*HD*NN];    // [B,H,d,n]   16MB (tf32-rounded)
__device__ float g_v [BB*HH*NN*HD];    // [B,H,n,d]   16MB (tf32-rounded)
__device__ float g_y [BB*NN*DD];       // [token, D]  16MB (tf32-rounded)
__device__ float g_x [BB*NN*DD];       // pre-rounded x      16MB
__device__ float g_wq[DD*3*DD];        // pre-rounded W_qkv   3MB
__device__ float g_wo[DD*DD];          // pre-rounded W_o     1MB
__device__ float g_biasT[(size_t)BB*HH*NN*NN];  // [B,H,q,k]*log2e 268MB

#define LOG2E 1.44269504088896340736f

__device__ __forceinline__ float cvt_tf32(float x) {
    uint32_t u;
    asm("cvt.rna.tf32.f32 %0, %1;" : "=r"(u) : "f"(x));
    return __uint_as_float(u);
}
__device__ __forceinline__ float ex2(float x) {
    float y;
    asm("ex2.approx.f32 %0, %1;" : "=f"(y) : "f"(x));
    return y;
}

#define MMA16N8K8(d, a0, a1, a2, a3, b0, b1)                              \
    asm volatile("mma.sync.aligned.m16n8k8.row.col.f32.tf32.tf32.f32 "    \
                 "{%0,%1,%2,%3},{%4,%5,%6,%7},{%8,%9},{%0,%1,%2,%3};"     \
                 : "+f"(d[0]), "+f"(d[1]), "+f"(d[2]), "+f"(d[3])         \
                 : "r"(a0), "r"(a1), "r"(a2), "r"(a3), "r"(b0), "r"(b1))

#define CP16(dst, src) \
    asm volatile("cp.async.cg.shared.global [%0], [%1], 16;" :: "r"(dst), "l"(src))
#define CP_COMMIT() asm volatile("cp.async.commit_group;")
#define CP_WAIT1()  asm volatile("cp.async.wait_group 1;")
#define CP_WAIT0()  asm volatile("cp.async.wait_group 0;")

// ---------------------------------------------------------------------------
// K-pre: elementwise tf32 rounding (float4 vectorized)
// ---------------------------------------------------------------------------
__global__ __launch_bounds__(256) void hp_cvt4(const float4* __restrict__ in,
                                               float4* __restrict__ out)
{
    const size_t i = (size_t)blockIdx.x * 256 + threadIdx.x;
    float4 t = in[i];
    t.x = cvt_tf32(t.x); t.y = cvt_tf32(t.y);
    t.z = cvt_tf32(t.z); t.w = cvt_tf32(t.w);
    out[i] = t;
}

// ---------------------------------------------------------------------------
// K0: bias transpose  [B][q][k][H] -> g_biasT [B][H][q*k], PRE-SCALED by log2e
// (base-2 softmax downstream). Persistent grid-stride (592 CTAs).
// ---------------------------------------------------------------------------
__global__ __launch_bounds__(256) void hp_bias_T(const float* __restrict__ bias)
{
    const size_t total  = (size_t)BB * 1048576;
    const size_t stride = (size_t)gridDim.x * 256;
    for (size_t idx = (size_t)blockIdx.x * 256 + threadIdx.x;
         idx < total; idx += stride) {
        const int    b  = (int)(idx >> 20);
        const size_t qk = idx & 1048575;
        const float4* p = (const float4*)(bias + (idx << 3));
        float4 t0 = p[0];
        float4 t1 = p[1];
        float* o = g_biasT + (size_t)b * 8388608 + qk;
        o[0 * 1048576] = t0.x * LOG2E; o[1 * 1048576] = t0.y * LOG2E;
        o[2 * 1048576] = t0.z * LOG2E; o[3 * 1048576] = t0.w * LOG2E;
        o[4 * 1048576] = t1.x * LOG2E; o[5 * 1048576] = t1.y * LOG2E;
        o[6 * 1048576] = t1.z * LOG2E; o[7 * 1048576] = t1.w * LOG2E;
    }
}

// ---------------------------------------------------------------------------
// K1/K3: tf32 HMMA GEMM (R8 config, unchanged).
// ---------------------------------------------------------------------------
template<int LDN, bool SPLIT>
__global__ __launch_bounds__(256, 2) void hp_gemm_mma(
    const float* __restrict__ A, const float* __restrict__ Wm,
    const float* __restrict__ bv, float* __restrict__ outp)
{
    extern __shared__ float sm[];
    float* As = sm;                 // [2][128*36]
    float* Bs = sm + 2 * 128 * 36;  // [2][32*136]

    const int tid  = threadIdx.x;
    const int warp = tid >> 5, lane = tid & 31;
    const int grp  = lane >> 2, tg = lane & 3;
    const int wm   = warp >> 1, wn = warp & 1;
    const int bm   = blockIdx.y * 128, bn = blockIdx.x * 128;

    const uint32_t sA = (uint32_t)__cvta_generic_to_shared(As);
    const uint32_t sB = (uint32_t)__cvta_generic_to_shared(Bs);

    float acc[2][8][4];
#pragma unroll
    for (int i = 0; i < 2; ++i)
#pragma unroll
        for (int j = 0; j < 8; ++j)
#pragma unroll
            for (int r = 0; r < 4; ++r) acc[i][j][r] = 0.f;

    auto load_tile = [&](int k0, int buf) {
#pragma unroll
        for (int i = 0; i < 4; ++i) {
            int v = i * 256 + tid;
            int r = v >> 3, c4 = (v & 7) << 2;
            CP16(sA + (buf * 128 * 36 + r * 36 + c4) * 4,
                 &A[(size_t)(bm + r) * 512 + k0 + c4]);
        }
#pragma unroll
        for (int i = 0; i < 4; ++i) {
            int v = i * 256 + tid;
            int r = v >> 5, c4 = (v & 31) << 2;
            CP16(sB + (buf * 32 * 136 + r * 136 + c4) * 4,
                 &Wm[(size_t)(k0 + r) * LDN + bn + c4]);
        }
    };

    load_tile(0, 0);
    CP_COMMIT();

    for (int it = 0; it < 16; ++it) {
        const int cur = it & 1;
        if (it < 15) {
            load_tile((it + 1) * 32, cur ^ 1);
            CP_COMMIT();
            CP_WAIT1();
        } else {
            CP_WAIT0();
        }
        __syncthreads();

        const float* Ac = As + cur * 128 * 36;
        const float* Bc = Bs + cur * 32 * 136;
#pragma unroll
        for (int ks = 0; ks < 4; ++ks) {
            const int kb = ks * 8;
            uint32_t a[2][4];
#pragma unroll
            for (int mf = 0; mf < 2; ++mf) {
                int r = wm * 32 + mf * 16 + grp;
                a[mf][0] = __float_as_uint(Ac[r * 36 + kb + tg]);
                a[mf][1] = __float_as_uint(Ac[(r + 8) * 36 + kb + tg]);
                a[mf][2] = __float_as_uint(Ac[r * 36 + kb + tg + 4]);
                a[mf][3] = __float_as_uint(Ac[(r + 8) * 36 + kb + tg + 4]);
            }
#pragma unroll
            for (int nf = 0; nf < 8; ++nf) {
                int c = wn * 64 + nf * 8 + grp;
                uint32_t b0 = __float_as_uint(Bc[(kb + tg) * 136 + c]);
                uint32_t b1 = __float_as_uint(Bc[(kb + tg + 4) * 136 + c]);
                MMA16N8K8(acc[0][nf], a[0][0], a[0][1], a[0][2], a[0][3], b0, b1);
                MMA16N8K8(acc[1][nf], a[1][0], a[1][1], a[1][2], a[1][3], b0, b1);
            }
        }
        __syncthreads();
    }

#pragma unroll
    for (int mf = 0; mf < 2; ++mf) {
#pragma unroll
        for (int rr = 0; rr < 2; ++rr) {
            const int m = bm + wm * 32 + mf * 16 + grp + rr * 8;
#pragma unroll
            for (int nf = 0; nf < 8; ++nf) {
                const int c = bn + wn * 64 + nf * 8 + tg * 2;
                float v0 = acc[mf][nf][rr * 2]     + bv[c];
                float v1 = acc[mf][nf][rr * 2 + 1] + bv[c + 1];
                if (SPLIT) {
                    v0 = cvt_tf32(v0);
                    v1 = cvt_tf32(v1);
                    int bi = m >> 10, n = m & 1023;
                    int h = c / 192, rem = c - h * 192;
                    int which = rem >> 6, t = rem & 63;
                    if (which == 0) {
                        g_qT[(((size_t)bi * 8 + h) * 64 + t)     * 1024 + n] = v0;
                        g_qT[(((size_t)bi * 8 + h) * 64 + t + 1) * 1024 + n] = v1;
                    } else if (which == 1) {
                        g_kT[(((size_t)bi * 8 + h) * 64 + t)     * 1024 + n] = v0;
                        g_kT[(((size_t)bi * 8 + h) * 64 + t + 1) * 1024 + n] = v1;
                    } else {
                        float2 w2 = make_float2(v0, v1);
                        *(float2*)&g_v[(((size_t)bi * 8 + h) * 1024 + n) * 64 + t] = w2;
                    }
                } else {
                    float2 w2 = make_float2(v0, v1);
                    *(float2*)&outp[(size_t)m * 512 + c] = w2;
                }
            }
        }
    }
}

// ---------------------------------------------------------------------------
// K2: flash attention, tf32 HMMA, software-pipelined: S(kt+1) MMAs issued
// BEFORE softmax(kt) so tensor work covers softmax latency per-warp.
// K/bias double-buffered, V triple-buffered; ONE barrier per iteration.
// Base-2 softmax (bias pre-scaled by log2e); lane-partial l, reduced at end.
// smem: Ks[2][64*40] + Bb[2][128*40] + Vs[3][32*72] + Ps[128*36] = 107.5KB
// ---------------------------------------------------------------------------
__global__ __launch_bounds__(256, 2) void hp_attn_mma()
{
    extern __shared__ float sm[];
    float* Ks = sm;                      // 2*2560 = 5120
    float* Bb = sm + 5120;               // 2*5120 = 10240
    float* Vs = sm + 15360;              // 3*2304 = 6912
    float* Ps = sm + 22272;              // 4608

    const int tid  = threadIdx.x;
    const int warp = tid >> 5, lane = tid & 31;
    const int grp  = lane >> 2, tg = lane & 3;
    const int h  = blockIdx.x;
    const int qt = blockIdx.y;
    const int b  = blockIdx.z;
    const int bh = b * HH + h;
    const int q0 = qt * 128;

    const uint32_t sK  = (uint32_t)__cvta_generic_to_shared(Ks);
    const uint32_t sBb = (uint32_t)__cvta_generic_to_shared(Bb);
    const uint32_t sV  = (uint32_t)__cvta_generic_to_shared(Vs);

    const float* kb = g_kT + (size_t)bh * HD * NN;
    const float* vbgl = g_v + (size_t)bh * NN * HD;
    const float* bias_bh = g_biasT + ((size_t)bh << 20);

    const int r0 = warp * 16 + grp;

    auto loadKB = [&](int k0, int buf) {
#pragma unroll
        for (int i = 0; i < 2; ++i) {                 // Ks: 64 x 32
            int v = i * 256 + tid;
            int d = v >> 3, c4 = (v & 7) << 2;
            CP16(sK + (buf * 2560 + d * 40 + c4) * 4,
                 &kb[(size_t)d * NN + k0 + c4]);
        }
#pragma unroll
        for (int i = 0; i < 4; ++i) {                 // Bb: 128 x 32
            int v = i * 256 + tid;
            int r = v >> 3, c4 = (v & 7) << 2;
            CP16(sBb + (buf * 5120 + r * 40 + c4) * 4,
                 &bias_bh[(size_t)(q0 + r) * 1024 + k0 + c4]);
        }
    };
    auto loadV = [&](int k0, int vb) {
#pragma unroll
        for (int i = 0; i < 2; ++i) {                 // Vs: 32 x 64
            int v = i * 256 + tid;
            int r = v >> 4, c4 = (v & 15) << 2;
            CP16(sV + (vb * 2304 + r * 72 + c4) * 4,
                 &vbgl[(size_t)(k0 + r) * HD + c4]);
        }
    };

    loadKB(0, 0); loadV(0, 0); CP_COMMIT();
    loadKB(32, 1); loadV(32, 1); CP_COMMIT();

    // Q fragments: fold 1/8 * log2e (re-rounded to tf32)
    const float QS = 0.125f * LOG2E;
    const float* qbase = g_qT + (size_t)bh * HD * NN;
    const int qr = q0 + warp * 16 + grp;
    uint32_t qa[8][4];
#pragma unroll
    for (int s = 0; s < 8; ++s) {
        int d0 = s * 8 + tg;
        qa[s][0] = __float_as_uint(cvt_tf32(qbase[(size_t)d0       * NN + qr]     * QS));
        qa[s][1] = __float_as_uint(cvt_tf32(qbase[(size_t)d0       * NN + qr + 8] * QS));
        qa[s][2] = __float_as_uint(cvt_tf32(qbase[(size_t)(d0 + 4) * NN + qr]     * QS));
        qa[s][3] = __float_as_uint(cvt_tf32(qbase[(size_t)(d0 + 4) * NN + qr + 8] * QS));
    }

    auto computeS = [&](float s_[4][4], const float* Kc, const float* Bc) {
#pragma unroll
        for (int nf = 0; nf < 4; ++nf)
#pragma unroll
            for (int r = 0; r < 4; ++r) s_[nf][r] = 0.f;
#pragma unroll
        for (int ks = 0; ks < 8; ++ks) {
#pragma unroll
            for (int nf = 0; nf < 4; ++nf) {
                int key = nf * 8 + grp;
                uint32_t b0 = __float_as_uint(Kc[(ks * 8 + tg) * 40 + key]);
                uint32_t b1 = __float_as_uint(Kc[(ks * 8 + tg + 4) * 40 + key]);
                MMA16N8K8(s_[nf], qa[ks][0], qa[ks][1], qa[ks][2], qa[ks][3], b0, b1);
            }
        }
#pragma unroll
        for (int nf = 0; nf < 4; ++nf) {
            int c = nf * 8 + tg * 2;
            float2 t0 = *(const float2*)&Bc[r0 * 40 + c];
            float2 t1 = *(const float2*)&Bc[(r0 + 8) * 40 + c];
            s_[nf][0] += t0.x; s_[nf][1] += t0.y;
            s_[nf][2] += t1.x; s_[nf][3] += t1.y;
        }
    };

    float o[8][4];
#pragma unroll
    for (int i = 0; i < 8; ++i)
#pragma unroll
        for (int j = 0; j < 4; ++j) o[i][j] = 0.f;
    float m0 = -1e30f, m1 = -1e30f, l0 = 0.f, l1 = 0.f;

    float s_c[4][4], s_n[4][4];

    // prologue: tile 0 resident -> S(0)
    CP_WAIT1();
    __syncthreads();
    computeS(s_c, Ks, Bb);

    int vb_cur = 0, vb_load = 2;

    for (int kt = 0; kt < 32; ++kt) {
        if (kt < 31) {
            CP_WAIT0();
            __syncthreads();   // tile kt+1 visible; all warps completed iter kt-1
            // S(kt+1): independent tensor work covering this iteration's softmax
            computeS(s_n, Ks + ((kt + 1) & 1) * 2560, Bb + ((kt + 1) & 1) * 5120);
            if (kt < 30) {
                loadKB((kt + 2) * 32, kt & 1);
                loadV((kt + 2) * 32, vb_load);
                CP_COMMIT();
            }
        }

        // ---- softmax on s_c (base-2 domain) ----
        float mx0 = -1e30f, mx1 = -1e30f;
#pragma unroll
        for (int nf = 0; nf < 4; ++nf) {
            mx0 = fmaxf(mx0, fmaxf(s_c[nf][0], s_c[nf][1]));
            mx1 = fmaxf(mx1, fmaxf(s_c[nf][2], s_c[nf][3]));
        }
        mx0 = fmaxf(mx0, __shfl_xor_sync(0xffffffffu, mx0, 1));
        mx0 = fmaxf(mx0, __shfl_xor_sync(0xffffffffu, mx0, 2));
        mx1 = fmaxf(mx1, __shfl_xor_sync(0xffffffffu, mx1, 1));
        mx1 = fmaxf(mx1, __shfl_xor_sync(0xffffffffu, mx1, 2));
        float mn0 = fmaxf(m0, mx0), mn1 = fmaxf(m1, mx1);
        float sc0 = ex2(m0 - mn0), sc1 = ex2(m1 - mn1);
        float sum0 = 0.f, sum1 = 0.f;
#pragma unroll
        for (int nf = 0; nf < 4; ++nf) {
            s_c[nf][0] = ex2(s_c[nf][0] - mn0);
            s_c[nf][1] = ex2(s_c[nf][1] - mn0);
            s_c[nf][2] = ex2(s_c[nf][2] - mn1);
            s_c[nf][3] = ex2(s_c[nf][3] - mn1);
            sum0 += s_c[nf][0] + s_c[nf][1];
            sum1 += s_c[nf][2] + s_c[nf][3];
        }
        l0 = l0 * sc0 + sum0;     // lane-partial; reduced after the loop
        l1 = l1 * sc1 + sum1;
        m0 = mn0; m1 = mn1;

        // rescale O
#pragma unroll
        for (int nf = 0; nf < 8; ++nf) {
            o[nf][0] *= sc0; o[nf][1] *= sc0;
            o[nf][2] *= sc1; o[nf][3] *= sc1;
        }

        // P -> smem (warp-private rows)
#pragma unroll
        for (int nf = 0; nf < 4; ++nf) {
            int c = nf * 8 + tg * 2;
            float2 p0 = make_float2(cvt_tf32(s_c[nf][0]), cvt_tf32(s_c[nf][1]));
            float2 p1 = make_float2(cvt_tf32(s_c[nf][2]), cvt_tf32(s_c[nf][3]));
            *(float2*)&Ps[r0 * 36 + c]       = p0;
            *(float2*)&Ps[(r0 + 8) * 36 + c] = p1;
        }
        __syncwarp();

        // O += P V
        const float* Vc = Vs + vb_cur * 2304;
#pragma unroll
        for (int ks = 0; ks < 4; ++ks) {
            uint32_t a0 = __float_as_uint(Ps[r0 * 36 + ks * 8 + tg]);
            uint32_t a1 = __float_as_uint(Ps[(r0 + 8) * 36 + ks * 8 + tg]);
            uint32_t a2 = __float_as_uint(Ps[r0 * 36 + ks * 8 + tg + 4]);
            uint32_t a3 = __float_as_uint(Ps[(r0 + 8) * 36 + ks * 8 + tg + 4]);
#pragma unroll
            for (int nf = 0; nf < 8; ++nf) {
                int dc = nf * 8 + grp;
                uint32_t b0 = __float_as_uint(Vc[(ks * 8 + tg) * 72 + dc]);
                uint32_t b1 = __float_as_uint(Vc[(ks * 8 + tg + 4) * 72 + dc]);
                MMA16N8K8(o[nf], a0, a1, a2, a3, b0, b1);
            }
        }

        // rotate register S buffers and V ring indices
#pragma unroll
        for (int nf = 0; nf < 4; ++nf)
#pragma unroll
            for (int r = 0; r < 4; ++r) s_c[nf][r] = s_n[nf][r];
        vb_cur  = (vb_cur  == 2) ? 0 : vb_cur + 1;
        vb_load = (vb_load == 2) ? 0 : vb_load + 1;
    }

    // final l reduction (deferred from the loop) + epilogue
    l0 += __shfl_xor_sync(0xffffffffu, l0, 1);
    l0 += __shfl_xor_sync(0xffffffffu, l0, 2);
    l1 += __shfl_xor_sync(0xffffffffu, l1, 1);
    l1 += __shfl_xor_sync(0xffffffffu, l1, 2);
    const float inv0 = 1.f / l0, inv1 = 1.f / l1;
    const size_t row0 = (size_t)b * NN + q0 + warp * 16 + grp;
    const size_t row1 = row0 + 8;
#pragma unroll
    for (int nf = 0; nf < 8; ++nf) {
        int c = h * 64 + nf * 8 + tg * 2;
        float2 w0 = make_float2(cvt_tf32(o[nf][0] * inv0), cvt_tf32(o[nf][1] * inv0));
        float2 w1 = make_float2(cvt_tf32(o[nf][2] * inv1), cvt_tf32(o[nf][3] * inv1));
        *(float2*)&g_y[row0 * DD + c] = w0;
        *(float2*)&g_y[row1 * DD + c] = w1;
    }
}

// ---------------------------------------------------------------------------
extern "C" void kernel_launch(void* const* d_in, const int* in_sizes, int n_in,
                              void* d_out, int out_size)
{
    const float* x    = (const float*)d_in[0];
    const float* bias = (const float*)d_in[1];
    const float* Wqkv = (const float*)d_in[2];
    const float* bqkv = (const float*)d_in[3];
    const float* Wo   = (const float*)d_in[4];
    const float* bo   = (const float*)d_in[5];
    float* out = (float*)d_out;

    const int gemm_smem = (2 * 128 * 36 + 2 * 32 * 136) * 4;  // 71680
    const int attn_smem = 26880 * 4;                          // 107520

    cudaFuncSetAttribute(hp_gemm_mma<1536, true>,
                         cudaFuncAttributeMaxDynamicSharedMemorySize, gemm_smem);
    cudaFuncSetAttribute(hp_gemm_mma<512, false>,
                         cudaFuncAttributeMaxDynamicSharedMemorySize, gemm_smem);
    cudaFuncSetAttribute(hp_attn_mma,
                         cudaFuncAttributeMaxDynamicSharedMemorySize, attn_smem);

    float* gx;  cudaGetSymbolAddress((void**)&gx,  g_x);
    float* gwq; cudaGetSymbolAddress((void**)&gwq, g_wq);
    float* gwo; cudaGetSymbolAddress((void**)&gwo, g_wo);
    float* gy;  cudaGetSymbolAddress((void**)&gy,  g_y);

    // Fork (R8 config): persistent bias transpose on side stream.
    cudaStream_t s1;
    cudaStreamCreateWithFlags(&s1, cudaStreamNonBlocking);
    cudaEvent_t eFork, eJoin;
    cudaEventCreateWithFlags(&eFork, cudaEventDisableTiming);
    cudaEventCreateWithFlags(&eJoin, cudaEventDisableTiming);

    cudaEventRecord(eFork, 0);
    cudaStreamWaitEvent(s1, eFork, 0);
    hp_bias_T<<<592, 256, 0, s1>>>(bias);
    cudaEventRecord(eJoin, s1);

    hp_cvt4<<<BB*NN*DD/4/256, 256>>>((const float4*)x,    (float4*)gx);
    hp_cvt4<<<DD*3*DD/4/256, 256>>>((const float4*)Wqkv, (float4*)gwq);
    hp_cvt4<<<DD*DD/4/256,   256>>>((const float4*)Wo,   (float4*)gwo);
    hp_gemm_mma<1536, true ><<<dim3(12, 64), 256, gemm_smem>>>(gx, gwq, bqkv, nullptr);

    cudaStreamWaitEvent(0, eJoin, 0);
    hp_attn_mma<<<dim3(HH, NN / 128, BB), 256, attn_smem>>>();
    hp_gemm_mma<512, false><<<dim3(4, 64), 256, gemm_smem>>>(gy, gwo, bo, out);

    cudaEventDestroy(eFork);
    cudaEventDestroy(eJoin);
    cudaStreamDestroy(s1);
}

// round 12
// speedup vs baseline: 1.0509x; 1.0509x over previous
#include <cuda_runtime.h>
#include <math.h>
#include <stdint.h>

#define BB 8
#define NN 1024
#define DD 512
#define HH 8
#define HD 64

__device__ float g_qT[BB*HH*HD*NN];    // [B,H,d,n]   16MB (tf32-rounded)
__device__ float g_kT[BB*HH*HD*NN];    // [B,H,d,n]   16MB (tf32-rounded)
__device__ float g_v [BB*HH*NN*HD];    // [B,H,n,d]   16MB (tf32-rounded)
__device__ float g_y [BB*NN*DD];       // [token, D]  16MB (tf32-rounded)
__device__ float g_x [BB*NN*DD];       // pre-rounded x      16MB
__device__ float g_wq[DD*3*DD];        // pre-rounded W_qkv   3MB
__device__ float g_wo[DD*DD];          // pre-rounded W_o     1MB
__device__ float g_biasT[(size_t)BB*HH*NN*NN];  // [B,H,q,k] 268MB

__device__ __forceinline__ float cvt_tf32(float x) {
    uint32_t u;
    asm("cvt.rna.tf32.f32 %0, %1;" : "=r"(u) : "f"(x));
    return __uint_as_float(u);
}

#define MMA16N8K8(d, a0, a1, a2, a3, b0, b1)                              \
    asm volatile("mma.sync.aligned.m16n8k8.row.col.f32.tf32.tf32.f32 "    \
                 "{%0,%1,%2,%3},{%4,%5,%6,%7},{%8,%9},{%0,%1,%2,%3};"     \
                 : "+f"(d[0]), "+f"(d[1]), "+f"(d[2]), "+f"(d[3])         \
                 : "r"(a0), "r"(a1), "r"(a2), "r"(a3), "r"(b0), "r"(b1))

#define CP16(dst, src) \
    asm volatile("cp.async.cg.shared.global [%0], [%1], 16;" :: "r"(dst), "l"(src))
#define CP_COMMIT() asm volatile("cp.async.commit_group;")
#define CP_WAIT1()  asm volatile("cp.async.wait_group 1;")
#define CP_WAIT0()  asm volatile("cp.async.wait_group 0;")

// ---------------------------------------------------------------------------
// K-pre: elementwise tf32 rounding (float4 vectorized)
// ---------------------------------------------------------------------------
__global__ __launch_bounds__(256) void hp_cvt4(const float4* __restrict__ in,
                                               float4* __restrict__ out)
{
    const size_t i = (size_t)blockIdx.x * 256 + threadIdx.x;
    float4 t = in[i];
    t.x = cvt_tf32(t.x); t.y = cvt_tf32(t.y);
    t.z = cvt_tf32(t.z); t.w = cvt_tf32(t.w);
    out[i] = t;
}

// ---------------------------------------------------------------------------
// K0: bias transpose  [B][q][k][H] -> g_biasT [B][H][q*k]
// Persistent grid-stride (592 CTAs) — R8 configuration.
// ---------------------------------------------------------------------------
__global__ __launch_bounds__(256) void hp_bias_T(const float* __restrict__ bias)
{
    const size_t total  = (size_t)BB * 1048576;
    const size_t stride = (size_t)gridDim.x * 256;
    for (size_t idx = (size_t)blockIdx.x * 256 + threadIdx.x;
         idx < total; idx += stride) {
        const int    b  = (int)(idx >> 20);
        const size_t qk = idx & 1048575;
        const float4* p = (const float4*)(bias + (idx << 3));
        float4 t0 = p[0];
        float4 t1 = p[1];
        float* o = g_biasT + (size_t)b * 8388608 + qk;
        o[0 * 1048576] = t0.x; o[1 * 1048576] = t0.y;
        o[2 * 1048576] = t0.z; o[3 * 1048576] = t0.w;
        o[4 * 1048576] = t1.x; o[5 * 1048576] = t1.y;
        o[6 * 1048576] = t1.z; o[7 * 1048576] = t1.w;
    }
}

// ---------------------------------------------------------------------------
// K1/K3: tf32 HMMA GEMM, BM=128, BN=128, BK=32, cp.async TRIPLE-buffered
// (2 tiles in flight during compute). One barrier per iteration:
//   WAIT1 -> sync (tile it visible AND buf (it-1)%3 free) -> issue(it+2) -> compute(it)
// ---------------------------------------------------------------------------
template<int LDN, bool SPLIT>
__global__ __launch_bounds__(256, 2) void hp_gemm_mma(
    const float* __restrict__ A, const float* __restrict__ Wm,
    const float* __restrict__ bv, float* __restrict__ outp)
{
    extern __shared__ float sm[];
    float* As = sm;                 // [3][128*36] = 13824 f
    float* Bs = sm + 3 * 128 * 36;  // [3][32*136] = 13056 f

    const int tid  = threadIdx.x;
    const int warp = tid >> 5, lane = tid & 31;
    const int grp  = lane >> 2, tg = lane & 3;
    const int wm   = warp >> 1, wn = warp & 1;
    const int bm   = blockIdx.y * 128, bn = blockIdx.x * 128;

    const uint32_t sA = (uint32_t)__cvta_generic_to_shared(As);
    const uint32_t sB = (uint32_t)__cvta_generic_to_shared(Bs);

    float acc[2][8][4];
#pragma unroll
    for (int i = 0; i < 2; ++i)
#pragma unroll
        for (int j = 0; j < 8; ++j)
#pragma unroll
            for (int r = 0; r < 4; ++r) acc[i][j][r] = 0.f;

    auto load_tile = [&](int k0, int buf) {
#pragma unroll
        for (int i = 0; i < 4; ++i) {
            int v = i * 256 + tid;
            int r = v >> 3, c4 = (v & 7) << 2;
            CP16(sA + (buf * 128 * 36 + r * 36 + c4) * 4,
                 &A[(size_t)(bm + r) * 512 + k0 + c4]);
        }
#pragma unroll
        for (int i = 0; i < 4; ++i) {
            int v = i * 256 + tid;
            int r = v >> 5, c4 = (v & 31) << 2;
            CP16(sB + (buf * 32 * 136 + r * 136 + c4) * 4,
                 &Wm[(size_t)(k0 + r) * LDN + bn + c4]);
        }
    };

    load_tile(0, 0);  CP_COMMIT();
    load_tile(32, 1); CP_COMMIT();

    int buf_cur = 0, buf_next2 = 2;
    for (int it = 0; it < 16; ++it) {
        if (it < 15) { CP_WAIT1(); } else { CP_WAIT0(); }
        __syncthreads();   // tile it visible everywhere; buf (it-1)%3 free
        if (it + 2 < 16) {
            load_tile((it + 2) * 32, buf_next2);
            CP_COMMIT();
        }

        const float* Ac = As + buf_cur * 128 * 36;
        const float* Bc = Bs + buf_cur * 32 * 136;
#pragma unroll
        for (int ks = 0; ks < 4; ++ks) {
            const int kb = ks * 8;
            uint32_t a[2][4];
#pragma unroll
            for (int mf = 0; mf < 2; ++mf) {
                int r = wm * 32 + mf * 16 + grp;
                a[mf][0] = __float_as_uint(Ac[r * 36 + kb + tg]);
                a[mf][1] = __float_as_uint(Ac[(r + 8) * 36 + kb + tg]);
                a[mf][2] = __float_as_uint(Ac[r * 36 + kb + tg + 4]);
                a[mf][3] = __float_as_uint(Ac[(r + 8) * 36 + kb + tg + 4]);
            }
#pragma unroll
            for (int nf = 0; nf < 8; ++nf) {
                int c = wn * 64 + nf * 8 + grp;
                uint32_t b0 = __float_as_uint(Bc[(kb + tg) * 136 + c]);
                uint32_t b1 = __float_as_uint(Bc[(kb + tg + 4) * 136 + c]);
                MMA16N8K8(acc[0][nf], a[0][0], a[0][1], a[0][2], a[0][3], b0, b1);
                MMA16N8K8(acc[1][nf], a[1][0], a[1][1], a[1][2], a[1][3], b0, b1);
            }
        }
        buf_cur   = (buf_cur   == 2) ? 0 : buf_cur + 1;
        buf_next2 = (buf_next2 == 2) ? 0 : buf_next2 + 1;
    }

#pragma unroll
    for (int mf = 0; mf < 2; ++mf) {
#pragma unroll
        for (int rr = 0; rr < 2; ++rr) {
            const int m = bm + wm * 32 + mf * 16 + grp + rr * 8;
#pragma unroll
            for (int nf = 0; nf < 8; ++nf) {
                const int c = bn + wn * 64 + nf * 8 + tg * 2;
                float v0 = acc[mf][nf][rr * 2]     + bv[c];
                float v1 = acc[mf][nf][rr * 2 + 1] + bv[c + 1];
                if (SPLIT) {
                    v0 = cvt_tf32(v0);
                    v1 = cvt_tf32(v1);
                    int bi = m >> 10, n = m & 1023;
                    int h = c / 192, rem = c - h * 192;
                    int which = rem >> 6, t = rem & 63;
                    if (which == 0) {
                        g_qT[(((size_t)bi * 8 + h) * 64 + t)     * 1024 + n] = v0;
                        g_qT[(((size_t)bi * 8 + h) * 64 + t + 1) * 1024 + n] = v1;
                    } else if (which == 1) {
                        g_kT[(((size_t)bi * 8 + h) * 64 + t)     * 1024 + n] = v0;
                        g_kT[(((size_t)bi * 8 + h) * 64 + t + 1) * 1024 + n] = v1;
                    } else {
                        float2 w2 = make_float2(v0, v1);
                        *(float2*)&g_v[(((size_t)bi * 8 + h) * 1024 + n) * 64 + t] = w2;
                    }
                } else {
                    float2 w2 = make_float2(v0, v1);
                    *(float2*)&outp[(size_t)m * 512 + c] = w2;
                }
            }
        }
    }
}

// ---------------------------------------------------------------------------
// K2: flash attention — EXACT R8 version (best measured).
// ---------------------------------------------------------------------------
__global__ __launch_bounds__(256, 2) void hp_attn_mma()
{
    extern __shared__ float sm[];
    float* Ks = sm;                      // 2*64*40  = 5120
    float* Vs = sm + 5120;               // 2*32*72  = 4608
    float* Bb = sm + 9728;               // 2*128*40 = 10240
    float* Ps = sm + 19968;              // 128*36   = 4608

    const int tid  = threadIdx.x;
    const int warp = tid >> 5, lane = tid & 31;
    const int grp  = lane >> 2, tg = lane & 3;
    const int h  = blockIdx.x;
    const int qt = blockIdx.y;
    const int b  = blockIdx.z;
    const int bh = b * HH + h;
    const int q0 = qt * 128;

    const uint32_t sK = (uint32_t)__cvta_generic_to_shared(Ks);
    const uint32_t sV = (uint32_t)__cvta_generic_to_shared(Vs);
    const uint32_t sBb = (uint32_t)__cvta_generic_to_shared(Bb);

    const float* kb = g_kT + (size_t)bh * HD * NN;
    const float* vb = g_v  + (size_t)bh * NN * HD;
    const float* bias_bh = g_biasT + ((size_t)bh << 20);

    auto load_tile = [&](int k0, int buf) {
#pragma unroll
        for (int i = 0; i < 2; ++i) {                 // Ks: 64 x 32
            int v = i * 256 + tid;
            int d = v >> 3, c4 = (v & 7) << 2;
            CP16(sK + (buf * 2560 + d * 40 + c4) * 4,
                 &kb[(size_t)d * NN + k0 + c4]);
        }
#pragma unroll
        for (int i = 0; i < 2; ++i) {                 // Vs: 32 x 64
            int v = i * 256 + tid;
            int r = v >> 4, c4 = (v & 15) << 2;
            CP16(sV + (buf * 2304 + r * 72 + c4) * 4,
                 &vb[(size_t)(k0 + r) * HD + c4]);
        }
#pragma unroll
        for (int i = 0; i < 4; ++i) {                 // Bb: 128 x 32
            int v = i * 256 + tid;
            int r = v >> 3, c4 = (v & 7) << 2;
            CP16(sBb + (buf * 5120 + r * 40 + c4) * 4,
                 &bias_bh[(size_t)(q0 + r) * 1024 + k0 + c4]);
        }
    };

    load_tile(0, 0);
    CP_COMMIT();

    const float* qbase = g_qT + (size_t)bh * HD * NN;
    const int qr = q0 + warp * 16 + grp;
    uint32_t qa[8][4];
#pragma unroll
    for (int s = 0; s < 8; ++s) {
        int d0 = s * 8 + tg;
        qa[s][0] = __float_as_uint(qbase[(size_t)d0       * NN + qr]     * 0.125f);
        qa[s][1] = __float_as_uint(qbase[(size_t)d0       * NN + qr + 8] * 0.125f);
        qa[s][2] = __float_as_uint(qbase[(size_t)(d0 + 4) * NN + qr]     * 0.125f);
        qa[s][3] = __float_as_uint(qbase[(size_t)(d0 + 4) * NN + qr + 8] * 0.125f);
    }

    float o[8][4];
#pragma unroll
    for (int i = 0; i < 8; ++i)
#pragma unroll
        for (int j = 0; j < 4; ++j) o[i][j] = 0.f;
    float m0 = -1e30f, m1 = -1e30f, l0 = 0.f, l1 = 0.f;

    const int r0 = warp * 16 + grp;

    for (int kt = 0; kt < 32; ++kt) {
        const int cur = kt & 1;
        if (kt < 31) {
            load_tile((kt + 1) * 32, cur ^ 1);
            CP_COMMIT();
            CP_WAIT1();
        } else {
            CP_WAIT0();
        }
        __syncthreads();

        const float* Kc = Ks + cur * 2560;
        const float* Vc = Vs + cur * 2304;
        const float* Bc = Bb + cur * 5120;

        float s_[4][4];
#pragma unroll
        for (int nf = 0; nf < 4; ++nf)
#pragma unroll
            for (int r = 0; r < 4; ++r) s_[nf][r] = 0.f;
#pragma unroll
        for (int ks = 0; ks < 8; ++ks) {
#pragma unroll
            for (int nf = 0; nf < 4; ++nf) {
                int key = nf * 8 + grp;
                uint32_t b0 = __float_as_uint(Kc[(ks * 8 + tg) * 40 + key]);
                uint32_t b1 = __float_as_uint(Kc[(ks * 8 + tg + 4) * 40 + key]);
                MMA16N8K8(s_[nf], qa[ks][0], qa[ks][1], qa[ks][2], qa[ks][3], b0, b1);
            }
        }
#pragma unroll
        for (int nf = 0; nf < 4; ++nf) {
            int c = nf * 8 + tg * 2;
            float2 t0 = *(const float2*)&Bc[r0 * 40 + c];
            float2 t1 = *(const float2*)&Bc[(r0 + 8) * 40 + c];
            s_[nf][0] += t0.x; s_[nf][1] += t0.y;
            s_[nf][2] += t1.x; s_[nf][3] += t1.y;
        }

        float mx0 = -1e30f, mx1 = -1e30f;
#pragma unroll
        for (int nf = 0; nf < 4; ++nf) {
            mx0 = fmaxf(mx0, fmaxf(s_[nf][0], s_[nf][1]));
            mx1 = fmaxf(mx1, fmaxf(s_[nf][2], s_[nf][3]));
        }
        mx0 = fmaxf(mx0, __shfl_xor_sync(0xffffffffu, mx0, 1));
        mx0 = fmaxf(mx0, __shfl_xor_sync(0xffffffffu, mx0, 2));
        mx1 = fmaxf(mx1, __shfl_xor_sync(0xffffffffu, mx1, 1));
        mx1 = fmaxf(mx1, __shfl_xor_sync(0xffffffffu, mx1, 2));
        float mn0 = fmaxf(m0, mx0), mn1 = fmaxf(m1, mx1);
        float sc0 = __expf(m0 - mn0), sc1 = __expf(m1 - mn1);
        float sum0 = 0.f, sum1 = 0.f;
#pragma unroll
        for (int nf = 0; nf < 4; ++nf) {
            s_[nf][0] = __expf(s_[nf][0] - mn0);
            s_[nf][1] = __expf(s_[nf][1] - mn0);
            s_[nf][2] = __expf(s_[nf][2] - mn1);
            s_[nf][3] = __expf(s_[nf][3] - mn1);
            sum0 += s_[nf][0] + s_[nf][1];
            sum1 += s_[nf][2] + s_[nf][3];
        }
        sum0 += __shfl_xor_sync(0xffffffffu, sum0, 1);
        sum0 += __shfl_xor_sync(0xffffffffu, sum0, 2);
        sum1 += __shfl_xor_sync(0xffffffffu, sum1, 1);
        sum1 += __shfl_xor_sync(0xffffffffu, sum1, 2);
        l0 = l0 * sc0 + sum0;
        l1 = l1 * sc1 + sum1;
        m0 = mn0; m1 = mn1;

#pragma unroll
        for (int nf = 0; nf < 8; ++nf) {
            o[nf][0] *= sc0; o[nf][1] *= sc0;
            o[nf][2] *= sc1; o[nf][3] *= sc1;
        }

#pragma unroll
        for (int nf = 0; nf < 4; ++nf) {
            int c = nf * 8 + tg * 2;
            float2 p0 = make_float2(cvt_tf32(s_[nf][0]), cvt_tf32(s_[nf][1]));
            float2 p1 = make_float2(cvt_tf32(s_[nf][2]), cvt_tf32(s_[nf][3]));
            *(float2*)&Ps[r0 * 36 + c]       = p0;
            *(float2*)&Ps[(r0 + 8) * 36 + c] = p1;
        }
        __syncwarp();

#pragma unroll
        for (int ks = 0; ks < 4; ++ks) {
            uint32_t a0 = __float_as_uint(Ps[r0 * 36 + ks * 8 + tg]);
            uint32_t a1 = __float_as_uint(Ps[(r0 + 8) * 36 + ks * 8 + tg]);
            uint32_t a2 = __float_as_uint(Ps[r0 * 36 + ks * 8 + tg + 4]);
            uint32_t a3 = __float_as_uint(Ps[(r0 + 8) * 36 + ks * 8 + tg + 4]);
#pragma unroll
            for (int nf = 0; nf < 8; ++nf) {
                int dc = nf * 8 + grp;
                uint32_t b0 = __float_as_uint(Vc[(ks * 8 + tg) * 72 + dc]);
                uint32_t b1 = __float_as_uint(Vc[(ks * 8 + tg + 4) * 72 + dc]);
                MMA16N8K8(o[nf], a0, a1, a2, a3, b0, b1);
            }
        }
        __syncthreads();
    }

    const float inv0 = 1.f / l0, inv1 = 1.f / l1;
    const size_t row0 = (size_t)b * NN + q0 + warp * 16 + grp;
    const size_t row1 = row0 + 8;
#pragma unroll
    for (int nf = 0; nf < 8; ++nf) {
        int c = h * 64 + nf * 8 + tg * 2;
        float2 w0 = make_float2(cvt_tf32(o[nf][0] * inv0), cvt_tf32(o[nf][1] * inv0));
        float2 w1 = make_float2(cvt_tf32(o[nf][2] * inv1), cvt_tf32(o[nf][3] * inv1));
        *(float2*)&g_y[row0 * DD + c] = w0;
        *(float2*)&g_y[row1 * DD + c] = w1;
    }
}

// ---------------------------------------------------------------------------
extern "C" void kernel_launch(void* const* d_in, const int* in_sizes, int n_in,
                              void* d_out, int out_size)
{
    const float* x    = (const float*)d_in[0];
    const float* bias = (const float*)d_in[1];
    const float* Wqkv = (const float*)d_in[2];
    const float* bqkv = (const float*)d_in[3];
    const float* Wo   = (const float*)d_in[4];
    const float* bo   = (const float*)d_in[5];
    float* out = (float*)d_out;

    const int gemm_smem = (3 * 128 * 36 + 3 * 32 * 136) * 4;  // 107520
    const int attn_smem = 24576 * 4;                          // 98304

    cudaFuncSetAttribute(hp_gemm_mma<1536, true>,
                         cudaFuncAttributeMaxDynamicSharedMemorySize, gemm_smem);
    cudaFuncSetAttribute(hp_gemm_mma<512, false>,
                         cudaFuncAttributeMaxDynamicSharedMemorySize, gemm_smem);
    cudaFuncSetAttribute(hp_attn_mma,
                         cudaFuncAttributeMaxDynamicSharedMemorySize, attn_smem);

    float* gx;  cudaGetSymbolAddress((void**)&gx,  g_x);
    float* gwq; cudaGetSymbolAddress((void**)&gwq, g_wq);
    float* gwo; cudaGetSymbolAddress((void**)&gwo, g_wo);
    float* gy;  cudaGetSymbolAddress((void**)&gy,  g_y);

    // Fork (R8 config): persistent bias transpose on side stream.
    cudaStream_t s1;
    cudaStreamCreateWithFlags(&s1, cudaStreamNonBlocking);
    cudaEvent_t eFork, eJoin;
    cudaEventCreateWithFlags(&eFork, cudaEventDisableTiming);
    cudaEventCreateWithFlags(&eJoin, cudaEventDisableTiming);

    cudaEventRecord(eFork, 0);
    cudaStreamWaitEvent(s1, eFork, 0);
    hp_bias_T<<<592, 256, 0, s1>>>(bias);
    cudaEventRecord(eJoin, s1);

    hp_cvt4<<<BB*NN*DD/4/256, 256>>>((const float4*)x,    (float4*)gx);
    hp_cvt4<<<DD*3*DD/4/256, 256>>>((const float4*)Wqkv, (float4*)gwq);
    hp_cvt4<<<DD*DD/4/256,   256>>>((const float4*)Wo,   (float4*)gwo);
    hp_gemm_mma<1536, true ><<<dim3(12, 64), 256, gemm_smem>>>(gx, gwq, bqkv, nullptr);

    cudaStreamWaitEvent(0, eJoin, 0);
    hp_attn_mma<<<dim3(HH, NN / 128, BB), 256, attn_smem>>>();
    hp_gemm_mma<512, false><<<dim3(4, 64), 256, gemm_smem>>>(gy, gwo, bo, out);

    cudaEventDestroy(eFork);
    cudaEventDestroy(eJoin);
    cudaStreamDestroy(s1);
}